// round 12
// baseline (speedup 1.0000x reference)
#include <cuda_runtime.h>
#include <cuda_bf16.h>
#include <math.h>

#define G     5000
#define IN_D  64
#define D     128
#define E     240000
#define NE    (E + G)       // edges + self loops
#define GD    (G * D)       // 640000
#define NB_MLP 1280
#define CH_MLP (GD / NB_MLP) // 500
#define NSLOT 64

// ---------------- scratch (device globals; no allocation allowed) -------------
__device__ float g_h[GD];
__device__ float g_xl[GD];
__device__ float g_xr[GD];
__device__ int   g_count[G];
__device__ int   g_start[G + 1];
__device__ int   g_cursor[G];
__device__ int   g_src[NE];
__device__ float g_e[NE];
__device__ float g_out[GD];
__device__ float g_ypart[NSLOT * D];
__device__ int   g_is64;

__device__ __forceinline__ float lrelu(float v) { return v > 0.f ? v : 0.2f * v; }

__device__ __forceinline__ int clampg(int v) {
    return v < 0 ? 0 : (v >= G ? G - 1 : v);
}

// Fetch edge endpoint i from either-int32-or-int64 storage.
// part = 0 -> src row, 1 -> dst row of the [2, E] edge_index.
__device__ __forceinline__ int edge_at(const void* ei, int is64, int part, int i) {
    if (is64) {
        const long long* p = (const long long*)ei;
        return clampg((int)p[(size_t)part * E + i]);
    } else {
        const int* p = (const int*)ei;
        return clampg(p[(size_t)part * E + i]);
    }
}

// ---------------- K0: zero per-launch state + detect edge dtype --------------
__global__ void k_init(const void* ei) {
    int i = blockIdx.x * blockDim.x + threadIdx.x;
    if (i < G) g_count[i] = 0;
    if (i < NSLOT * D) g_ypart[i] = 0.f;
    if (i == 0) {
        // Inspect first 128 words interpreted as int64. Genuine int64 edges are
        // all in [0, G). int32 data reinterpreted as int64 packs two edges per
        // word; such a word is >= 2^32 unless the high int32 happens to be 0.
        const unsigned long long* p = (const unsigned long long*)ei;
        int ok64 = 1;
        for (int k = 0; k < 128; k++) {
            if (p[k] >= (unsigned long long)G) { ok64 = 0; break; }
        }
        g_is64 = ok64;
    }
}

// ---------------- K1: h = relu(x . W_in + b_in), one block per gene ----------
__global__ void __launch_bounds__(128) k_h(const float* __restrict__ x,
                                           const float* __restrict__ Win,
                                           const float* __restrict__ bin) {
    int g = blockIdx.x;
    int d = threadIdx.x;
    __shared__ float xs[IN_D];
    if (d < IN_D) xs[d] = x[g * IN_D + d];
    __syncthreads();
    const float* w = Win + (size_t)g * IN_D * D + d;
    float acc = 0.f;
#pragma unroll 8
    for (int i = 0; i < IN_D; i++) acc = fmaf(xs[i], w[(size_t)i * D], acc);
    acc += bin[g * D + d];
    g_h[g * D + d] = fmaxf(acc, 0.f);
}

// ---------------- K2: xl = h.Wl + bl ; xr = h.Wr + br (row-tiled) ------------
#define ROWS 32
__global__ void __launch_bounds__(256) k_xlxr(const float* __restrict__ Wl,
                                              const float* __restrict__ bl,
                                              const float* __restrict__ Wr,
                                              const float* __restrict__ br) {
    __shared__ float hs[ROWS][D];
    int g0 = blockIdx.x * ROWS;
    int tid = threadIdx.x;
    for (int idx = tid; idx < ROWS * D; idx += 256) {
        int r = idx / D, c = idx % D;
        hs[r][c] = (g0 + r < G) ? g_h[(g0 + r) * D + c] : 0.f;
    }
    __syncthreads();
    int half = tid >> 7;          // 0 -> l, 1 -> r
    int d = tid & 127;
    const float* W = half ? Wr : Wl;
    const float* b = half ? br : bl;
    float* o = half ? g_xr : g_xl;
    float acc[ROWS];
#pragma unroll
    for (int r = 0; r < ROWS; r++) acc[r] = 0.f;
    for (int k = 0; k < D; k++) {
        float wv = W[k * D + d];
#pragma unroll
        for (int r = 0; r < ROWS; r++) acc[r] = fmaf(hs[r][k], wv, acc[r]);
    }
    float bv = b[d];
#pragma unroll
    for (int r = 0; r < ROWS; r++)
        if (g0 + r < G) o[(g0 + r) * D + d] = acc[r] + bv;
}

// ---------------- K3: histogram of destination degrees -----------------------
__global__ void k_hist(const void* __restrict__ ei) {
    int i = blockIdx.x * blockDim.x + threadIdx.x;
    if (i >= NE) return;
    int is64 = g_is64;
    int dst = (i < E) ? edge_at(ei, is64, 1, i) : (i - E);
    atomicAdd(&g_count[dst], 1);
}

// ---------------- K4: exclusive scan (single block) --------------------------
__global__ void __launch_bounds__(1024) k_scan() {
    __shared__ int sh[1024];
    __shared__ int carry_s;
    int tid = threadIdx.x;
    if (tid == 0) carry_s = 0;
    __syncthreads();
    for (int base = 0; base < G; base += 1024) {
        int v = (base + tid < G) ? g_count[base + tid] : 0;
        sh[tid] = v;
        __syncthreads();
        for (int off = 1; off < 1024; off <<= 1) {
            int t = (tid >= off) ? sh[tid - off] : 0;
            __syncthreads();
            sh[tid] += t;
            __syncthreads();
        }
        int carry = carry_s;
        int excl = carry + sh[tid] - v;
        if (base + tid < G) { g_start[base + tid] = excl; g_cursor[base + tid] = excl; }
        __syncthreads();
        if (tid == 0) carry_s = carry + sh[1023];
        __syncthreads();
    }
    if (tid == 0) g_start[G] = carry_s;
}

// ---------------- K5: bucket edges by destination ----------------------------
__global__ void k_scatter(const void* __restrict__ ei) {
    int i = blockIdx.x * blockDim.x + threadIdx.x;
    if (i >= NE) return;
    int is64 = g_is64;
    int src, dst;
    if (i < E) { src = edge_at(ei, is64, 0, i); dst = edge_at(ei, is64, 1, i); }
    else       { src = i - E;                   dst = i - E; }
    int pos = atomicAdd(&g_cursor[dst], 1);
    if (pos < NE) g_src[pos] = src;
}

// ---------------- K6: fused attention + softmax + aggregate ------------------
__global__ void __launch_bounds__(128) k_agg(const float* __restrict__ att,
                                             const float* __restrict__ bias) {
    int g = blockIdx.x;
    int tid = threadIdx.x;
    int lane = tid & 31, warp = tid >> 5;
    __shared__ float xr_sh[D], att_sh[D], red[D];
    __shared__ float m_sh, z_sh;
    xr_sh[tid] = g_xr[g * D + tid];
    att_sh[tid] = att[tid];
    __syncthreads();
    int s0 = g_start[g], s1 = g_start[g + 1];

    // pass 1: logits, warp per edge
    for (int p = s0 + warp; p < s1; p += 4) {
        const float* xlp = g_xl + (size_t)g_src[p] * D;
        float acc = 0.f;
#pragma unroll
        for (int q = 0; q < 4; q++) {
            int d = lane + q * 32;
            float v = xlp[d] + xr_sh[d];
            v = v > 0.f ? v : 0.2f * v;
            acc = fmaf(att_sh[d], v, acc);
        }
#pragma unroll
        for (int off = 16; off > 0; off >>= 1)
            acc += __shfl_down_sync(0xffffffffu, acc, off);
        if (lane == 0) g_e[p] = acc;
    }
    __syncthreads();

    // segment max
    float mx = -1e30f;
    for (int p = s0 + tid; p < s1; p += 128) mx = fmaxf(mx, g_e[p]);
    red[tid] = mx; __syncthreads();
#pragma unroll
    for (int off = 64; off > 0; off >>= 1) {
        if (tid < off) red[tid] = fmaxf(red[tid], red[tid + off]);
        __syncthreads();
    }
    if (tid == 0) m_sh = red[0];
    __syncthreads();
    float m = m_sh;

    // exp + segment sum
    float s = 0.f;
    for (int p = s0 + tid; p < s1; p += 128) {
        float w = __expf(g_e[p] - m);
        g_e[p] = w;
        s += w;
    }
    red[tid] = s; __syncthreads();
#pragma unroll
    for (int off = 64; off > 0; off >>= 1) {
        if (tid < off) red[tid] += red[tid + off];
        __syncthreads();
    }
    if (tid == 0) z_sh = red[0];
    __syncthreads();
    float zinv = 1.f / z_sh;
    for (int p = s0 + tid; p < s1; p += 128) g_e[p] *= zinv;
    __syncthreads();

    // pass 2: weighted aggregate, thread = feature d
    float a0 = 0.f, a1 = 0.f, a2 = 0.f, a3 = 0.f;
    int p = s0;
    for (; p + 3 < s1; p += 4) {
        a0 = fmaf(g_e[p],     g_xl[(size_t)g_src[p]     * D + tid], a0);
        a1 = fmaf(g_e[p + 1], g_xl[(size_t)g_src[p + 1] * D + tid], a1);
        a2 = fmaf(g_e[p + 2], g_xl[(size_t)g_src[p + 2] * D + tid], a2);
        a3 = fmaf(g_e[p + 3], g_xl[(size_t)g_src[p + 3] * D + tid], a3);
    }
    for (; p < s1; p++) a0 = fmaf(g_e[p], g_xl[(size_t)g_src[p] * D + tid], a0);
    float o = a0 + a1 + a2 + a3 + bias[tid];
    g_out[g * D + tid] = lrelu(o);
}

// ---------------- K7: y = flat . W1 (streaming matvec) -----------------------
__global__ void __launch_bounds__(128) k_mlp(const float* __restrict__ W1) {
    int j = threadIdx.x;
    int b = blockIdx.x;
    int n0 = b * CH_MLP;
    int n1 = n0 + CH_MLP;
    float acc = 0.f;
#pragma unroll 16
    for (int n = n0; n < n1; n++)
        acc = fmaf(g_out[n], W1[(size_t)n * D + j], acc);
    atomicAdd(&g_ypart[(b & (NSLOT - 1)) * D + j], acc);
}

// ---------------- K8: relu(y + b1) . W2 + b2 ---------------------------------
__global__ void __launch_bounds__(128) k_final(const float* __restrict__ b1,
                                               const float* __restrict__ W2,
                                               const float* __restrict__ b2,
                                               float* __restrict__ out) {
    int j = threadIdx.x;
    float v = b1[j];
#pragma unroll 8
    for (int s = 0; s < NSLOT; s++) v += g_ypart[s * D + j];
    v = fmaxf(v, 0.f);
    __shared__ float red[D];
    red[j] = v * W2[j];
    __syncthreads();
#pragma unroll
    for (int off = 64; off > 0; off >>= 1) {
        if (j < off) red[j] += red[j + off];
        __syncthreads();
    }
    if (j == 0) out[0] = red[0] + b2[0];
}

// -----------------------------------------------------------------------------
extern "C" void kernel_launch(void* const* d_in, const int* in_sizes, int n_in,
                              void* d_out, int out_size) {
    const float* x    = (const float*)d_in[0];
    const void*  ei   = d_in[1];                 // int32 or int64, detected on device
    const float* Win  = (const float*)d_in[2];
    const float* bin  = (const float*)d_in[3];
    const float* Wl   = (const float*)d_in[4];
    const float* bl   = (const float*)d_in[5];
    const float* Wr   = (const float*)d_in[6];
    const float* br   = (const float*)d_in[7];
    const float* att  = (const float*)d_in[8];
    const float* bias = (const float*)d_in[9];
    const float* W1   = (const float*)d_in[10];
    const float* b1   = (const float*)d_in[11];
    const float* W2   = (const float*)d_in[12];
    const float* b2   = (const float*)d_in[13];
    float* out = (float*)d_out;

    k_init<<<(NSLOT * D + 255) / 256, 256>>>(ei);   // 8192 threads >= max(G, NSLOT*D); also dtype-detect
    k_h<<<G, 128>>>(x, Win, bin);
    k_xlxr<<<(G + ROWS - 1) / ROWS, 256>>>(Wl, bl, Wr, br);
    k_hist<<<(NE + 255) / 256, 256>>>(ei);
    k_scan<<<1, 1024>>>();
    k_scatter<<<(NE + 255) / 256, 256>>>(ei);
    k_agg<<<G, 128>>>(att, bias);
    k_mlp<<<NB_MLP, 128>>>(W1);
    k_final<<<1, 128>>>(b1, W2, b2, out);
}

// round 17
// speedup vs baseline: 1.0278x; 1.0278x over previous
#include <cuda_runtime.h>
#include <cuda_bf16.h>
#include <math.h>

#define G     5000
#define IN_D  64
#define D     128
#define E     240000
#define NE    (E + G)       // edges + self loops
#define GD    (G * D)       // 640000
#define NB_MLP 1280
#define CH_MLP (GD / NB_MLP) // 500
#define NSLOT 64
#define MAXDEG 2048         // smem logit staging bound (true max deg ~90)

// ---------------- scratch (device globals; no allocation allowed) -------------
__device__ float g_h[GD];
__device__ float g_xl[GD];
__device__ float g_xr[GD];
__device__ int   g_count[G];
__device__ int   g_start[G + 1];
__device__ int   g_cursor[G];
__device__ int   g_src[NE];
__device__ float g_e[NE];        // fallback only (deg > MAXDEG)
__device__ float g_out[GD];
__device__ float g_ypart[NSLOT * D];
__device__ int   g_is64;

__device__ __forceinline__ float lrelu(float v) { return v > 0.f ? v : 0.2f * v; }

__device__ __forceinline__ int clampg(int v) {
    return v < 0 ? 0 : (v >= G ? G - 1 : v);
}

__device__ __forceinline__ int edge_at(const void* ei, int is64, int part, int i) {
    if (is64) {
        const long long* p = (const long long*)ei;
        return clampg((int)p[(size_t)part * E + i]);
    } else {
        const int* p = (const int*)ei;
        return clampg(p[(size_t)part * E + i]);
    }
}

// ---------------- K0: init state + detect edge dtype --------------------------
// g_count starts at 1: each node's self-loop is pre-counted, so k_hist only
// has to histogram the E real edges.
__global__ void k_init(const void* ei) {
    int i = blockIdx.x * blockDim.x + threadIdx.x;
    if (i < G) g_count[i] = 1;
    if (i < NSLOT * D) g_ypart[i] = 0.f;
    if (i == 0) {
        const unsigned long long* p = (const unsigned long long*)ei;
        int ok64 = 1;
        for (int k = 0; k < 128; k++) {
            if (p[k] >= (unsigned long long)G) { ok64 = 0; break; }
        }
        g_is64 = ok64;
    }
}

// ---------------- K1: h = relu(x . W_in + b_in) -------------------------------
__global__ void __launch_bounds__(128) k_h(const float* __restrict__ x,
                                           const float* __restrict__ Win,
                                           const float* __restrict__ bin) {
    int g = blockIdx.x;
    int d = threadIdx.x;
    __shared__ float xs[IN_D];
    if (d < IN_D) xs[d] = x[g * IN_D + d];
    __syncthreads();
    const float* w = Win + (size_t)g * IN_D * D + d;
    float acc = 0.f;
#pragma unroll 8
    for (int i = 0; i < IN_D; i++) acc = fmaf(xs[i], w[(size_t)i * D], acc);
    acc += bin[g * D + d];
    g_h[g * D + d] = fmaxf(acc, 0.f);
}

// ---------------- K2: xl = h.Wl + bl ; xr = h.Wr + br -------------------------
#define ROWS 32
__global__ void __launch_bounds__(256) k_xlxr(const float* __restrict__ Wl,
                                              const float* __restrict__ bl,
                                              const float* __restrict__ Wr,
                                              const float* __restrict__ br) {
    __shared__ float hs[ROWS][D];
    int g0 = blockIdx.x * ROWS;
    int tid = threadIdx.x;
    for (int idx = tid; idx < ROWS * D; idx += 256) {
        int r = idx / D, c = idx % D;
        hs[r][c] = (g0 + r < G) ? g_h[(g0 + r) * D + c] : 0.f;
    }
    __syncthreads();
    int half = tid >> 7;
    int d = tid & 127;
    const float* W = half ? Wr : Wl;
    const float* b = half ? br : bl;
    float* o = half ? g_xr : g_xl;
    float acc[ROWS];
#pragma unroll
    for (int r = 0; r < ROWS; r++) acc[r] = 0.f;
    for (int k = 0; k < D; k++) {
        float wv = W[k * D + d];
#pragma unroll
        for (int r = 0; r < ROWS; r++) acc[r] = fmaf(hs[r][k], wv, acc[r]);
    }
    float bv = b[d];
#pragma unroll
    for (int r = 0; r < ROWS; r++)
        if (g0 + r < G) o[(g0 + r) * D + d] = acc[r] + bv;
}

// ---------------- K3: histogram of real-edge destinations (4 per thread) -----
__global__ void k_hist(const void* __restrict__ ei) {
    int base = (blockIdx.x * blockDim.x + threadIdx.x) * 4;
    if (base >= E) return;
    int is64 = g_is64;
    int d0 = -1, d1 = -1, d2 = -1, d3 = -1;
    d0 = edge_at(ei, is64, 1, base);
    if (base + 1 < E) d1 = edge_at(ei, is64, 1, base + 1);
    if (base + 2 < E) d2 = edge_at(ei, is64, 1, base + 2);
    if (base + 3 < E) d3 = edge_at(ei, is64, 1, base + 3);
    atomicAdd(&g_count[d0], 1);
    if (d1 >= 0) atomicAdd(&g_count[d1], 1);
    if (d2 >= 0) atomicAdd(&g_count[d2], 1);
    if (d3 >= 0) atomicAdd(&g_count[d3], 1);
}

// ---------------- K4: exclusive scan, warp-shuffle based ----------------------
__global__ void __launch_bounds__(1024) k_scan() {
    __shared__ int warp_sums[32];
    __shared__ int carry_s;
    int tid = threadIdx.x;
    int lane = tid & 31, wid = tid >> 5;
    if (tid == 0) carry_s = 0;
    __syncthreads();
    for (int base = 0; base < G; base += 1024) {
        int v = (base + tid < G) ? g_count[base + tid] : 0;
        int x = v;
#pragma unroll
        for (int off = 1; off < 32; off <<= 1) {
            int t = __shfl_up_sync(0xffffffffu, x, off);
            if (lane >= off) x += t;
        }
        if (lane == 31) warp_sums[wid] = x;
        __syncthreads();
        if (wid == 0) {
            int ws = warp_sums[lane];
#pragma unroll
            for (int off = 1; off < 32; off <<= 1) {
                int t = __shfl_up_sync(0xffffffffu, ws, off);
                if (lane >= off) ws += t;
            }
            warp_sums[lane] = ws;   // inclusive warp-sum scan
        }
        __syncthreads();
        int carry = carry_s;
        int warp_off = (wid > 0) ? warp_sums[wid - 1] : 0;
        int excl = carry + warp_off + x - v;
        if (base + tid < G) { g_start[base + tid] = excl; g_cursor[base + tid] = excl; }
        int total = warp_sums[31];
        __syncthreads();
        if (tid == 0) carry_s = carry + total;
        __syncthreads();
    }
    if (tid == 0) g_start[G] = carry_s;
}

// ---------------- K5: bucket edges by destination (4 per thread) --------------
__global__ void k_scatter(const void* __restrict__ ei) {
    int base = (blockIdx.x * blockDim.x + threadIdx.x) * 4;
    if (base >= NE) return;
    int is64 = g_is64;
#pragma unroll
    for (int k = 0; k < 4; k++) {
        int i = base + k;
        if (i >= NE) break;
        int src, dst;
        if (i < E) { src = edge_at(ei, is64, 0, i); dst = edge_at(ei, is64, 1, i); }
        else       { src = i - E;                   dst = i - E; }
        int pos = atomicAdd(&g_cursor[dst], 1);
        if (pos < NE) g_src[pos] = src;
    }
}

// ---------------- K6: fused attention + softmax + aggregate (smem logits) ----
__global__ void __launch_bounds__(128) k_agg(const float* __restrict__ att,
                                             const float* __restrict__ bias) {
    int g = blockIdx.x;
    int tid = threadIdx.x;
    int lane = tid & 31, warp = tid >> 5;
    __shared__ float xr_sh[D], att_sh[D];
    __shared__ float e_sh[MAXDEG];
    __shared__ float rmax[4], rsum[4];
    xr_sh[tid] = g_xr[g * D + tid];
    att_sh[tid] = att[tid];
    __syncthreads();
    int s0 = g_start[g], s1 = g_start[g + 1];
    int deg = s1 - s0;
    bool insm = (deg <= MAXDEG);

    // pass 1: logits, warp per edge
    for (int p = s0 + warp; p < s1; p += 4) {
        const float* xlp = g_xl + (size_t)g_src[p] * D;
        float acc = 0.f;
#pragma unroll
        for (int q = 0; q < 4; q++) {
            int d = lane + q * 32;
            float v = xlp[d] + xr_sh[d];
            v = v > 0.f ? v : 0.2f * v;
            acc = fmaf(att_sh[d], v, acc);
        }
#pragma unroll
        for (int off = 16; off > 0; off >>= 1)
            acc += __shfl_down_sync(0xffffffffu, acc, off);
        if (lane == 0) { if (insm) e_sh[p - s0] = acc; else g_e[p] = acc; }
    }
    __syncthreads();

    // segment max (shuffle reduce, 1 barrier)
    float mx = -1e30f;
    for (int q = tid; q < deg; q += 128)
        mx = fmaxf(mx, insm ? e_sh[q] : g_e[s0 + q]);
#pragma unroll
    for (int off = 16; off > 0; off >>= 1)
        mx = fmaxf(mx, __shfl_xor_sync(0xffffffffu, mx, off));
    if (lane == 0) rmax[warp] = mx;
    __syncthreads();
    mx = fmaxf(fmaxf(rmax[0], rmax[1]), fmaxf(rmax[2], rmax[3]));

    // exp + segment sum (no normalize sweep: fold 1/z into the aggregate)
    float s = 0.f;
    for (int q = tid; q < deg; q += 128) {
        float w = __expf((insm ? e_sh[q] : g_e[s0 + q]) - mx);
        if (insm) e_sh[q] = w; else g_e[s0 + q] = w;
        s += w;
    }
#pragma unroll
    for (int off = 16; off > 0; off >>= 1)
        s += __shfl_xor_sync(0xffffffffu, s, off);
    if (lane == 0) rsum[warp] = s;
    __syncthreads();
    float zinv = 1.f / (rsum[0] + rsum[1] + rsum[2] + rsum[3]);

    // pass 2: weighted aggregate, thread = feature d
    float a0 = 0.f, a1 = 0.f, a2 = 0.f, a3 = 0.f;
    int p = s0;
    if (insm) {
        for (; p + 3 < s1; p += 4) {
            a0 = fmaf(e_sh[p - s0],     g_xl[(size_t)g_src[p]     * D + tid], a0);
            a1 = fmaf(e_sh[p - s0 + 1], g_xl[(size_t)g_src[p + 1] * D + tid], a1);
            a2 = fmaf(e_sh[p - s0 + 2], g_xl[(size_t)g_src[p + 2] * D + tid], a2);
            a3 = fmaf(e_sh[p - s0 + 3], g_xl[(size_t)g_src[p + 3] * D + tid], a3);
        }
        for (; p < s1; p++) a0 = fmaf(e_sh[p - s0], g_xl[(size_t)g_src[p] * D + tid], a0);
    } else {
        for (; p + 3 < s1; p += 4) {
            a0 = fmaf(g_e[p],     g_xl[(size_t)g_src[p]     * D + tid], a0);
            a1 = fmaf(g_e[p + 1], g_xl[(size_t)g_src[p + 1] * D + tid], a1);
            a2 = fmaf(g_e[p + 2], g_xl[(size_t)g_src[p + 2] * D + tid], a2);
            a3 = fmaf(g_e[p + 3], g_xl[(size_t)g_src[p + 3] * D + tid], a3);
        }
        for (; p < s1; p++) a0 = fmaf(g_e[p], g_xl[(size_t)g_src[p] * D + tid], a0);
    }
    float o = (a0 + a1 + a2 + a3) * zinv + bias[tid];
    g_out[g * D + tid] = lrelu(o);
}

// ---------------- K7: y = flat . W1 (streaming matvec) ------------------------
__global__ void __launch_bounds__(128) k_mlp(const float* __restrict__ W1) {
    int j = threadIdx.x;
    int b = blockIdx.x;
    int n0 = b * CH_MLP;
    int n1 = n0 + CH_MLP;
    float acc = 0.f;
#pragma unroll 16
    for (int n = n0; n < n1; n++)
        acc = fmaf(g_out[n], W1[(size_t)n * D + j], acc);
    atomicAdd(&g_ypart[(b & (NSLOT - 1)) * D + j], acc);
}

// ---------------- K8: relu(y + b1) . W2 + b2 ----------------------------------
__global__ void __launch_bounds__(128) k_final(const float* __restrict__ b1,
                                               const float* __restrict__ W2,
                                               const float* __restrict__ b2,
                                               float* __restrict__ out) {
    int j = threadIdx.x;
    float v = b1[j];
#pragma unroll 8
    for (int s = 0; s < NSLOT; s++) v += g_ypart[s * D + j];
    v = fmaxf(v, 0.f);
    __shared__ float red[D];
    red[j] = v * W2[j];
    __syncthreads();
#pragma unroll
    for (int off = 64; off > 0; off >>= 1) {
        if (j < off) red[j] += red[j + off];
        __syncthreads();
    }
    if (j == 0) out[0] = red[0] + b2[0];
}

// -----------------------------------------------------------------------------
extern "C" void kernel_launch(void* const* d_in, const int* in_sizes, int n_in,
                              void* d_out, int out_size) {
    const float* x    = (const float*)d_in[0];
    const void*  ei   = d_in[1];
    const float* Win  = (const float*)d_in[2];
    const float* bin  = (const float*)d_in[3];
    const float* Wl   = (const float*)d_in[4];
    const float* bl   = (const float*)d_in[5];
    const float* Wr   = (const float*)d_in[6];
    const float* br   = (const float*)d_in[7];
    const float* att  = (const float*)d_in[8];
    const float* bias = (const float*)d_in[9];
    const float* W1   = (const float*)d_in[10];
    const float* b1   = (const float*)d_in[11];
    const float* W2   = (const float*)d_in[12];
    const float* b2   = (const float*)d_in[13];
    float* out = (float*)d_out;

    k_init<<<(NSLOT * D + 255) / 256, 256>>>(ei);
    k_h<<<G, 128>>>(x, Win, bin);
    k_xlxr<<<(G + ROWS - 1) / ROWS, 256>>>(Wl, bl, Wr, br);
    k_hist<<<(E / 4 + 255) / 256, 256>>>(ei);
    k_scan<<<1, 1024>>>();
    k_scatter<<<(NE / 4 + 255) / 256, 256>>>(ei);
    k_agg<<<G, 128>>>(att, bias);
    k_mlp<<<NB_MLP, 128>>>(W1);
    k_final<<<1, 128>>>(b1, W2, b2, out);
}